// round 1
// baseline (speedup 1.0000x reference)
#include <cuda_runtime.h>

#define NUM_E 100000
#define DZ    384
#define MEMD  256
#define NODED 128

#define BM 64
#define BN 64
#define KB 32
#define E_PAD 100032   // 1563 * 64, padded edge count for GEMM tiles

// Scratch: scaled z vectors per edge (written by gather kernel, read by GEMM).
__device__ float g_zs[(size_t)E_PAD * DZ];
__device__ float g_zp[(size_t)E_PAD * DZ];
__device__ float g_zn[(size_t)E_PAD * DZ];

// ---------------------------------------------------------------------------
// Kernel A: per-edge gather + Jodie scaling + m_src/m_pos passthrough outputs.
// One block (128 threads) per edge.
// ---------------------------------------------------------------------------
__global__ void gather_scale(
    const float* __restrict__ mem, const float* __restrict__ lu,
    const float* __restrict__ x,   const float* __restrict__ bt,
    const float* __restrict__ wps, const float* __restrict__ bps,
    const float* __restrict__ wpd, const float* __restrict__ bpd,
    const float* __restrict__ bfin,
    const int* __restrict__ nid,   const int* __restrict__ idmap,
    const int* __restrict__ src,   const int* __restrict__ pdst,
    const int* __restrict__ ndst,
    float* __restrict__ out)
{
    int e = blockIdx.x;
    int t = threadIdx.x;

    __shared__ int   s_g[3];
    __shared__ float s_rt[3];

    if (t == 0) {
        float btv = bt[e];
        int gs = nid[idmap[src[e]]];
        int gp = nid[idmap[pdst[e]]];
        int gn = nid[idmap[ndst[e]]];
        s_g[0] = gs; s_g[1] = gp; s_g[2] = gn;
        s_rt[0] = fabsf(lu[gs] - btv);
        s_rt[1] = fabsf(lu[gp] - btv);
        s_rt[2] = fabsf(lu[gn] - btv);
        // seed the scalar outputs with b_final; GEMM kernel atomically adds.
        out[e]         = bfin[0];
        out[NUM_E + e] = bfin[0];
    }
    __syncthreads();

    int gs = s_g[0], gp = s_g[1], gn = s_g[2];
    float rts = s_rt[0], rtp = s_rt[1], rtn = s_rt[2];

    size_t zoff = (size_t)e * DZ;
    float* msrc = out + 2 * NUM_E + (size_t)e * MEMD;
    float* mpos = out + 2 * NUM_E + (size_t)NUM_E * MEMD + (size_t)e * MEMD;

    for (int c = t; c < DZ; c += 128) {
        float zs, zp, zn;
        if (c < MEMD) {
            zs = mem[(size_t)gs * MEMD + c];
            zp = mem[(size_t)gp * MEMD + c];
            zn = mem[(size_t)gn * MEMD + c];
            msrc[c] = zs;   // raw memory passthrough outputs
            mpos[c] = zp;
        } else {
            zs = x[(size_t)gs * NODED + (c - MEMD)];
            zp = x[(size_t)gp * NODED + (c - MEMD)];
            zn = x[(size_t)gn * NODED + (c - MEMD)];
        }
        g_zs[zoff + c] = zs * (1.0f + rts * wps[c] + bps[c]);
        g_zp[zoff + c] = zp * (1.0f + rtp * wpd[c] + bpd[c]);
        g_zn[zoff + c] = zn * (1.0f + rtn * wpd[c] + bpd[c]);
    }
}

// ---------------------------------------------------------------------------
// Kernel B: fused triple GEMM + bias + ReLU + final-dot readout.
//   C_common = Zsrc @ Wl^T   (shared between pos and neg)
//   C_pos    = Zpos @ Wd^T
//   C_neg    = Zneg @ Wd^T
//   pos[e] += sum_j relu(C_common + C_pos + bl[j] + bd[j]) * wf[j]
// Tiles: BM=64 edges x BN=64 channels, K chunks of 32. 256 threads, 4x4 micro.
// Partial j-range sums reduced via shfl and atomicAdd'ed across the 6 N-blocks.
// ---------------------------------------------------------------------------
__global__ __launch_bounds__(256) void gemm_readout(
    const float* __restrict__ wl, const float* __restrict__ wd,
    const float* __restrict__ bl, const float* __restrict__ bd,
    const float* __restrict__ wf,
    float* __restrict__ out)
{
    __shared__ float sZs[KB][BM + 1];
    __shared__ float sZp[KB][BM + 1];
    __shared__ float sZn[KB][BM + 1];
    __shared__ float sWl[KB][BN + 1];
    __shared__ float sWd[KB][BN + 1];

    int tid = threadIdx.x;
    int tx = tid & 15;       // N direction
    int ty = tid >> 4;       // M direction
    int m0 = blockIdx.y * BM;
    int n0 = blockIdx.x * BN;

    float aC[4][4] = {}, aP[4][4] = {}, aN[4][4] = {};

    for (int k0 = 0; k0 < DZ; k0 += KB) {
        // --- load tiles (each thread: 2 x float4 per matrix) ---
        #pragma unroll
        for (int p = 0; p < 2; p++) {
            int idx = tid + p * 256;
            int row = idx >> 3;           // 0..63
            int c4  = (idx & 7) * 4;      // 0,4,...,28

            size_t ga = (size_t)(m0 + row) * DZ + k0 + c4;
            float4 v;
            v = *(const float4*)(g_zs + ga);
            sZs[c4 + 0][row] = v.x; sZs[c4 + 1][row] = v.y;
            sZs[c4 + 2][row] = v.z; sZs[c4 + 3][row] = v.w;
            v = *(const float4*)(g_zp + ga);
            sZp[c4 + 0][row] = v.x; sZp[c4 + 1][row] = v.y;
            sZp[c4 + 2][row] = v.z; sZp[c4 + 3][row] = v.w;
            v = *(const float4*)(g_zn + ga);
            sZn[c4 + 0][row] = v.x; sZn[c4 + 1][row] = v.y;
            sZn[c4 + 2][row] = v.z; sZn[c4 + 3][row] = v.w;

            size_t gw = (size_t)(n0 + row) * DZ + k0 + c4;
            v = *(const float4*)(wl + gw);
            sWl[c4 + 0][row] = v.x; sWl[c4 + 1][row] = v.y;
            sWl[c4 + 2][row] = v.z; sWl[c4 + 3][row] = v.w;
            v = *(const float4*)(wd + gw);
            sWd[c4 + 0][row] = v.x; sWd[c4 + 1][row] = v.y;
            sWd[c4 + 2][row] = v.z; sWd[c4 + 3][row] = v.w;
        }
        __syncthreads();

        #pragma unroll
        for (int kk = 0; kk < KB; kk++) {
            float zs[4], zp[4], zn[4], wa[4], wb[4];
            #pragma unroll
            for (int i = 0; i < 4; i++) {
                zs[i] = sZs[kk][ty * 4 + i];
                zp[i] = sZp[kk][ty * 4 + i];
                zn[i] = sZn[kk][ty * 4 + i];
            }
            #pragma unroll
            for (int j = 0; j < 4; j++) {
                wa[j] = sWl[kk][tx * 4 + j];
                wb[j] = sWd[kk][tx * 4 + j];
            }
            #pragma unroll
            for (int i = 0; i < 4; i++)
                #pragma unroll
                for (int j = 0; j < 4; j++) {
                    aC[i][j] += zs[i] * wa[j];
                    aP[i][j] += zp[i] * wb[j];
                    aN[i][j] += zn[i] * wb[j];
                }
        }
        __syncthreads();
    }

    // --- epilogue: bias + relu + final dot over this block's j range ---
    float pp[4] = {0.f, 0.f, 0.f, 0.f};
    float pn[4] = {0.f, 0.f, 0.f, 0.f};
    #pragma unroll
    for (int j = 0; j < 4; j++) {
        int n = n0 + tx * 4 + j;
        float bias = bl[n] + bd[n];
        float wfj  = wf[n];
        #pragma unroll
        for (int i = 0; i < 4; i++) {
            float hp = aC[i][j] + aP[i][j] + bias;
            float hn = aC[i][j] + aN[i][j] + bias;
            pp[i] += fmaxf(hp, 0.f) * wfj;
            pn[i] += fmaxf(hn, 0.f) * wfj;
        }
    }

    // reduce across the 16 tx lanes (they form contiguous 16-lane halves of a warp)
    #pragma unroll
    for (int s = 1; s < 16; s <<= 1) {
        #pragma unroll
        for (int i = 0; i < 4; i++) {
            pp[i] += __shfl_xor_sync(0xffffffffu, pp[i], s);
            pn[i] += __shfl_xor_sync(0xffffffffu, pn[i], s);
        }
    }
    if (tx == 0) {
        #pragma unroll
        for (int i = 0; i < 4; i++) {
            int e = m0 + ty * 4 + i;
            if (e < NUM_E) {
                atomicAdd(&out[e],         pp[i]);
                atomicAdd(&out[NUM_E + e], pn[i]);
            }
        }
    }
}

// ---------------------------------------------------------------------------
extern "C" void kernel_launch(void* const* d_in, const int* in_sizes, int n_in,
                              void* d_out, int out_size) {
    const float* mem  = (const float*)d_in[0];   // memory_table [500000,256]
    const float* lu   = (const float*)d_in[1];   // last_update  [500000]
    const float* x    = (const float*)d_in[2];   // x            [500000,128]
    const float* bt   = (const float*)d_in[3];   // batch_t      [E]
    const float* wps  = (const float*)d_in[4];   // wp_src [384,1]
    const float* bps  = (const float*)d_in[5];   // bp_src [384]
    const float* wpd  = (const float*)d_in[6];   // wp_dst [384,1]
    const float* bpd  = (const float*)d_in[7];   // bp_dst [384]
    const float* wl   = (const float*)d_in[8];   // w_lsrc [384,384]
    const float* bl   = (const float*)d_in[9];   // b_lsrc [384]
    const float* wd   = (const float*)d_in[10];  // w_ldst [384,384]
    const float* bd   = (const float*)d_in[11];  // b_ldst [384]
    const float* wf   = (const float*)d_in[12];  // w_final [1,384]
    const float* bf   = (const float*)d_in[13];  // b_final [1]
    const int*   nid  = (const int*)d_in[14];    // n_id [300000]
    const int*   idm  = (const int*)d_in[15];    // id_mapper [500000]
    const int*   src  = (const int*)d_in[16];    // src [E]
    const int*   pds  = (const int*)d_in[17];    // pos_dst [E]
    const int*   nds  = (const int*)d_in[18];    // neg_dst [E]
    float* out = (float*)d_out;

    gather_scale<<<NUM_E, 128>>>(mem, lu, x, bt, wps, bps, wpd, bpd, bf,
                                 nid, idm, src, pds, nds, out);

    dim3 grid(DZ / BN, (NUM_E + BM - 1) / BM);  // (6, 1563)
    gemm_readout<<<grid, 256>>>(wl, wd, bl, bd, wf, out);
}

// round 2
// speedup vs baseline: 2.2691x; 2.2691x over previous
#include <cuda_runtime.h>
#include <cstdint>

#define NUM_E 100000
#define DZ    384
#define MEMD  256
#define NODED 128
#define E_PAD 100096           // 782 * 128
#define BM 128
#define BN 64
#define KB 16
#define NCH (DZ/KB)            // 24 k-chunks

#define ZSTR 20                // padded row stride (floats) -> conflict-free quad LDS
#define WSTR 20
#define ZBUF (3*128*ZSTR)      // 7680 floats per Z buffer
#define WBUF (2*64*WSTR)       // 2560 floats per W buffer
#define ZTOT (2*ZBUF)          // 15360
#define SMEM_BYTES ((ZTOT + 2*WBUF)*4)   // 81920 B

// Scratch (zero-initialized .bss; rows >= NUM_E stay zero = safe padding)
__device__ float g_zs[(size_t)E_PAD * DZ];
__device__ float g_zp[(size_t)E_PAD * DZ];
__device__ float g_zn[(size_t)E_PAD * DZ];
__device__ float g_wl[DZ * DZ];
__device__ float g_wd[DZ * DZ];

__device__ __forceinline__ float tf32r(float v) {
    uint32_t u;
    asm("cvt.rna.tf32.f32 %0, %1;" : "=r"(u) : "f"(v));
    return __uint_as_float(u);
}

__device__ __forceinline__ void mma_tf32(float* c,
    uint32_t a0, uint32_t a1, uint32_t a2, uint32_t a3,
    uint32_t b0, uint32_t b1)
{
    asm volatile(
        "mma.sync.aligned.m16n8k8.row.col.f32.tf32.tf32.f32 "
        "{%0,%1,%2,%3},{%4,%5,%6,%7},{%8,%9},{%0,%1,%2,%3};"
        : "+f"(c[0]), "+f"(c[1]), "+f"(c[2]), "+f"(c[3])
        : "r"(a0), "r"(a1), "r"(a2), "r"(a3), "r"(b0), "r"(b1));
}

// ---------------------------------------------------------------------------
// Weight pre-round to tf32 (RN) into scratch.
// ---------------------------------------------------------------------------
__global__ void convw(const float* __restrict__ wl, const float* __restrict__ wd) {
    int i = blockIdx.x * blockDim.x + threadIdx.x;
    if (i < DZ * DZ) {
        g_wl[i] = tf32r(wl[i]);
        g_wd[i] = tf32r(wd[i]);
    }
}

// ---------------------------------------------------------------------------
// Kernel A: per-edge gather + Jodie scaling (tf32-rounded) + m passthroughs.
// ---------------------------------------------------------------------------
__global__ void gather_scale(
    const float* __restrict__ mem, const float* __restrict__ lu,
    const float* __restrict__ x,   const float* __restrict__ bt,
    const float* __restrict__ wps, const float* __restrict__ bps,
    const float* __restrict__ wpd, const float* __restrict__ bpd,
    const float* __restrict__ bfin,
    const int* __restrict__ nid,   const int* __restrict__ idmap,
    const int* __restrict__ src,   const int* __restrict__ pdst,
    const int* __restrict__ ndst,
    float* __restrict__ out)
{
    int e = blockIdx.x;
    int t = threadIdx.x;

    __shared__ int   s_g[3];
    __shared__ float s_rt[3];

    if (t == 0) {
        float btv = bt[e];
        int gs = nid[idmap[src[e]]];
        int gp = nid[idmap[pdst[e]]];
        int gn = nid[idmap[ndst[e]]];
        s_g[0] = gs; s_g[1] = gp; s_g[2] = gn;
        s_rt[0] = fabsf(lu[gs] - btv);
        s_rt[1] = fabsf(lu[gp] - btv);
        s_rt[2] = fabsf(lu[gn] - btv);
        out[e]         = bfin[0];   // seed with b_final; GEMM atomically adds
        out[NUM_E + e] = bfin[0];
    }
    __syncthreads();

    int gs = s_g[0], gp = s_g[1], gn = s_g[2];
    float rts = s_rt[0], rtp = s_rt[1], rtn = s_rt[2];

    size_t zoff = (size_t)e * DZ;
    float* msrc = out + 2 * NUM_E + (size_t)e * MEMD;
    float* mpos = out + 2 * NUM_E + (size_t)NUM_E * MEMD + (size_t)e * MEMD;

    for (int c = t; c < DZ; c += 128) {
        float zs, zp, zn;
        if (c < MEMD) {
            zs = mem[(size_t)gs * MEMD + c];
            zp = mem[(size_t)gp * MEMD + c];
            zn = mem[(size_t)gn * MEMD + c];
            msrc[c] = zs;
            mpos[c] = zp;
        } else {
            zs = x[(size_t)gs * NODED + (c - MEMD)];
            zp = x[(size_t)gp * NODED + (c - MEMD)];
            zn = x[(size_t)gn * NODED + (c - MEMD)];
        }
        g_zs[zoff + c] = tf32r(zs * (1.0f + rts * wps[c] + bps[c]));
        g_zp[zoff + c] = tf32r(zp * (1.0f + rtp * wpd[c] + bpd[c]));
        g_zn[zoff + c] = tf32r(zn * (1.0f + rtn * wpd[c] + bpd[c]));
    }
}

// ---------------------------------------------------------------------------
// Kernel B: fused triple tf32 tensor-core GEMM + bias/ReLU/final-dot readout.
// Block tile 128x64, 8 warps (4M x 2N), warp tile 32x32 (m16n8k8 x 2x4),
// 3 accumulator sets (common/pos/neg), double-buffered cp.async K-pipeline.
// ---------------------------------------------------------------------------
__global__ __launch_bounds__(256) void gemm_readout(
    const float* __restrict__ bl, const float* __restrict__ bd,
    const float* __restrict__ wf, float* __restrict__ out)
{
    extern __shared__ float sm[];
    uint32_t sbase = (uint32_t)__cvta_generic_to_shared(sm);

    int tid  = threadIdx.x;
    int wid  = tid >> 5, lane = tid & 31;
    int grp  = lane >> 2, qid = lane & 3;
    int wm   = wid & 3,  wn  = wid >> 2;
    int m0   = blockIdx.y * BM;
    int n0   = blockIdx.x * BN;

    const float* zsrc[3] = { g_zs, g_zp, g_zn };
    const float* wsrc[2] = { g_wl, g_wd };

    float acc[3][2][4][4];
    #pragma unroll
    for (int a = 0; a < 3; a++)
        #pragma unroll
        for (int b = 0; b < 2; b++)
            #pragma unroll
            for (int c = 0; c < 4; c++)
                #pragma unroll
                for (int d = 0; d < 4; d++) acc[a][b][c][d] = 0.f;

    auto load_chunk = [&](int ch, int buf) {
        int k0 = ch * KB;
        #pragma unroll
        for (int p = 0; p < 6; p++) {           // Z: 3 mats * 128 rows * 4 f4
            int id  = tid + p * 256;
            int mat = id >> 9;
            int rem = id & 511;
            int row = rem >> 2;
            int kc  = (rem & 3) << 2;
            const float* src = zsrc[mat] + (size_t)(m0 + row) * DZ + k0 + kc;
            uint32_t dst = sbase + (uint32_t)((buf * ZBUF + (mat * 128 + row) * ZSTR + kc) * 4);
            asm volatile("cp.async.ca.shared.global [%0], [%1], 16;" :: "r"(dst), "l"(src));
        }
        #pragma unroll
        for (int p = 0; p < 2; p++) {           // W: 2 mats * 64 rows * 4 f4
            int id  = tid + p * 256;
            int mat = id >> 8;
            int rem = id & 255;
            int n   = rem >> 2;
            int kc  = (rem & 3) << 2;
            const float* src = wsrc[mat] + (size_t)(n0 + n) * DZ + k0 + kc;
            uint32_t dst = sbase + (uint32_t)((ZTOT + buf * WBUF + (mat * 64 + n) * WSTR + kc) * 4);
            asm volatile("cp.async.ca.shared.global [%0], [%1], 16;" :: "r"(dst), "l"(src));
        }
        asm volatile("cp.async.commit_group;");
    };

    load_chunk(0, 0);
    int buf = 0;
    for (int ch = 0; ch < NCH; ch++) {
        if (ch + 1 < NCH) {
            load_chunk(ch + 1, buf ^ 1);
            asm volatile("cp.async.wait_group 1;");
        } else {
            asm volatile("cp.async.wait_group 0;");
        }
        __syncthreads();

        const float* zb = sm + buf * ZBUF;
        const float* wb = sm + ZTOT + buf * WBUF;

        #pragma unroll
        for (int kk = 0; kk < KB; kk += 8) {
            uint32_t afr[3][2][4];
            uint32_t bfr[2][4][2];
            #pragma unroll
            for (int mat = 0; mat < 3; mat++)
                #pragma unroll
                for (int mt = 0; mt < 2; mt++) {
                    int r = wm * 32 + mt * 16 + grp;
                    const float* base = zb + mat * 128 * ZSTR;
                    afr[mat][mt][0] = __float_as_uint(base[(r    ) * ZSTR + kk + qid]);
                    afr[mat][mt][1] = __float_as_uint(base[(r + 8) * ZSTR + kk + qid]);
                    afr[mat][mt][2] = __float_as_uint(base[(r    ) * ZSTR + kk + qid + 4]);
                    afr[mat][mt][3] = __float_as_uint(base[(r + 8) * ZSTR + kk + qid + 4]);
                }
            #pragma unroll
            for (int mat = 0; mat < 2; mat++)
                #pragma unroll
                for (int nt = 0; nt < 4; nt++) {
                    int n = wn * 32 + nt * 8 + grp;
                    const float* base = wb + mat * 64 * WSTR;
                    bfr[mat][nt][0] = __float_as_uint(base[n * WSTR + kk + qid]);
                    bfr[mat][nt][1] = __float_as_uint(base[n * WSTR + kk + qid + 4]);
                }
            #pragma unroll
            for (int mt = 0; mt < 2; mt++)
                #pragma unroll
                for (int nt = 0; nt < 4; nt++) {
                    mma_tf32(acc[0][mt][nt], afr[0][mt][0], afr[0][mt][1], afr[0][mt][2], afr[0][mt][3], bfr[0][nt][0], bfr[0][nt][1]);
                    mma_tf32(acc[1][mt][nt], afr[1][mt][0], afr[1][mt][1], afr[1][mt][2], afr[1][mt][3], bfr[1][nt][0], bfr[1][nt][1]);
                    mma_tf32(acc[2][mt][nt], afr[2][mt][0], afr[2][mt][1], afr[2][mt][2], afr[2][mt][3], bfr[1][nt][0], bfr[1][nt][1]);
                }
        }
        __syncthreads();
        buf ^= 1;
    }

    // --- epilogue: bias + relu + final-dot partials over this block's N range ---
    float pp[2][2] = {{0.f,0.f},{0.f,0.f}};
    float pn[2][2] = {{0.f,0.f},{0.f,0.f}};
    #pragma unroll
    for (int nt = 0; nt < 4; nt++) {
        #pragma unroll
        for (int j = 0; j < 2; j++) {
            int n = n0 + wn * 32 + nt * 8 + 2 * qid + j;
            float bias = bl[n] + bd[n];
            float wfn  = wf[n];
            #pragma unroll
            for (int mt = 0; mt < 2; mt++) {
                float c0 = acc[0][mt][nt][j]     + acc[1][mt][nt][j]     + bias;
                float c1 = acc[0][mt][nt][2 + j] + acc[1][mt][nt][2 + j] + bias;
                pp[mt][0] += fmaxf(c0, 0.f) * wfn;
                pp[mt][1] += fmaxf(c1, 0.f) * wfn;
                float d0 = acc[0][mt][nt][j]     + acc[2][mt][nt][j]     + bias;
                float d1 = acc[0][mt][nt][2 + j] + acc[2][mt][nt][2 + j] + bias;
                pn[mt][0] += fmaxf(d0, 0.f) * wfn;
                pn[mt][1] += fmaxf(d1, 0.f) * wfn;
            }
        }
    }
    // reduce across the quad (lanes sharing a row)
    #pragma unroll
    for (int s = 1; s < 4; s <<= 1) {
        #pragma unroll
        for (int mt = 0; mt < 2; mt++) {
            pp[mt][0] += __shfl_xor_sync(0xffffffffu, pp[mt][0], s);
            pp[mt][1] += __shfl_xor_sync(0xffffffffu, pp[mt][1], s);
            pn[mt][0] += __shfl_xor_sync(0xffffffffu, pn[mt][0], s);
            pn[mt][1] += __shfl_xor_sync(0xffffffffu, pn[mt][1], s);
        }
    }
    if (qid == 0) {
        #pragma unroll
        for (int mt = 0; mt < 2; mt++)
            #pragma unroll
            for (int rh = 0; rh < 2; rh++) {
                int e = m0 + wm * 32 + mt * 16 + rh * 8 + grp;
                if (e < NUM_E) {
                    atomicAdd(&out[e],         pp[mt][rh]);
                    atomicAdd(&out[NUM_E + e], pn[mt][rh]);
                }
            }
    }
}

// ---------------------------------------------------------------------------
extern "C" void kernel_launch(void* const* d_in, const int* in_sizes, int n_in,
                              void* d_out, int out_size) {
    const float* mem  = (const float*)d_in[0];
    const float* lu   = (const float*)d_in[1];
    const float* x    = (const float*)d_in[2];
    const float* bt   = (const float*)d_in[3];
    const float* wps  = (const float*)d_in[4];
    const float* bps  = (const float*)d_in[5];
    const float* wpd  = (const float*)d_in[6];
    const float* bpd  = (const float*)d_in[7];
    const float* wl   = (const float*)d_in[8];
    const float* bl   = (const float*)d_in[9];
    const float* wd   = (const float*)d_in[10];
    const float* bd   = (const float*)d_in[11];
    const float* wf   = (const float*)d_in[12];
    const float* bf   = (const float*)d_in[13];
    const int*   nid  = (const int*)d_in[14];
    const int*   idm  = (const int*)d_in[15];
    const int*   src  = (const int*)d_in[16];
    const int*   pds  = (const int*)d_in[17];
    const int*   nds  = (const int*)d_in[18];
    float* out = (float*)d_out;

    cudaFuncSetAttribute(gemm_readout,
                         cudaFuncAttributeMaxDynamicSharedMemorySize, SMEM_BYTES);

    convw<<<(DZ * DZ + 255) / 256, 256>>>(wl, wd);
    gather_scale<<<NUM_E, 128>>>(mem, lu, x, bt, wps, bps, wpd, bpd, bf,
                                 nid, idm, src, pds, nds, out);

    dim3 grid(DZ / BN, E_PAD / BM);   // (6, 782)
    gemm_readout<<<grid, 256, SMEM_BYTES>>>(bl, bd, wf, out);
}

// round 4
// speedup vs baseline: 3.8340x; 1.6897x over previous
#include <cuda_runtime.h>
#include <cuda_fp16.h>
#include <cstdint>

#define NUM_E 100000
#define DZ    384
#define MEMD  256
#define NODED 128
#define E_PAD 100096           // 782 * 128
#define BM 128
#define BN 64
#define KB 32                  // K halves per chunk
#define NCH (DZ/KB)            // 12 chunks

#define ZSTR 40                // padded row stride in halves (80 B) -> conflict-free
#define WSTR 40
#define ZBUF (3*128*ZSTR)      // 15360 halves per Z buffer
#define WBUF (2*64*WSTR)       // 5120 halves per W buffer
#define ZTOT (2*ZBUF)          // 30720
#define SMEM_BYTES ((ZTOT + 2*WBUF)*2)   // 81920 B

// fp16 scratch (zero-initialized .bss; rows >= NUM_E stay zero = safe padding)
__device__ __align__(16) __half g_zs[(size_t)E_PAD * DZ];
__device__ __align__(16) __half g_zp[(size_t)E_PAD * DZ];
__device__ __align__(16) __half g_zn[(size_t)E_PAD * DZ];
__device__ __align__(16) __half g_wl[DZ * DZ];
__device__ __align__(16) __half g_wd[DZ * DZ];

__device__ __forceinline__ void mma_f16(float* c,
    uint32_t a0, uint32_t a1, uint32_t a2, uint32_t a3,
    uint32_t b0, uint32_t b1)
{
    asm volatile(
        "mma.sync.aligned.m16n8k16.row.col.f32.f16.f16.f32 "
        "{%0,%1,%2,%3},{%4,%5,%6,%7},{%8,%9},{%0,%1,%2,%3};"
        : "+f"(c[0]), "+f"(c[1]), "+f"(c[2]), "+f"(c[3])
        : "r"(a0), "r"(a1), "r"(a2), "r"(a3), "r"(b0), "r"(b1));
}

// ---------------------------------------------------------------------------
// Weight conversion to fp16.
// ---------------------------------------------------------------------------
__global__ void convw(const float* __restrict__ wl, const float* __restrict__ wd) {
    int i = blockIdx.x * blockDim.x + threadIdx.x;
    if (i < DZ * DZ) {
        g_wl[i] = __float2half_rn(wl[i]);
        g_wd[i] = __float2half_rn(wd[i]);
    }
}

// ---------------------------------------------------------------------------
// Kernel A: per-edge gather + Jodie scaling -> fp16 scratch + m passthroughs.
// ---------------------------------------------------------------------------
__global__ void gather_scale(
    const float* __restrict__ mem, const float* __restrict__ lu,
    const float* __restrict__ x,   const float* __restrict__ bt,
    const float* __restrict__ wps, const float* __restrict__ bps,
    const float* __restrict__ wpd, const float* __restrict__ bpd,
    const float* __restrict__ bfin,
    const int* __restrict__ nid,   const int* __restrict__ idmap,
    const int* __restrict__ src,   const int* __restrict__ pdst,
    const int* __restrict__ ndst,
    float* __restrict__ out)
{
    int e = blockIdx.x;
    int t = threadIdx.x;

    __shared__ int   s_g[3];
    __shared__ float s_rt[3];

    if (t == 0) {
        float btv = bt[e];
        int gs = nid[idmap[src[e]]];
        int gp = nid[idmap[pdst[e]]];
        int gn = nid[idmap[ndst[e]]];
        s_g[0] = gs; s_g[1] = gp; s_g[2] = gn;
        s_rt[0] = fabsf(lu[gs] - btv);
        s_rt[1] = fabsf(lu[gp] - btv);
        s_rt[2] = fabsf(lu[gn] - btv);
        out[e]         = bfin[0];   // seed with b_final; GEMM atomically adds
        out[NUM_E + e] = bfin[0];
    }
    __syncthreads();

    int gs = s_g[0], gp = s_g[1], gn = s_g[2];
    float rts = s_rt[0], rtp = s_rt[1], rtn = s_rt[2];

    size_t zoff = (size_t)e * DZ;
    float* msrc = out + 2 * NUM_E + (size_t)e * MEMD;
    float* mpos = out + 2 * NUM_E + (size_t)NUM_E * MEMD + (size_t)e * MEMD;

    for (int c = t; c < DZ; c += 128) {
        float zs, zp, zn;
        if (c < MEMD) {
            zs = mem[(size_t)gs * MEMD + c];
            zp = mem[(size_t)gp * MEMD + c];
            zn = mem[(size_t)gn * MEMD + c];
            msrc[c] = zs;
            mpos[c] = zp;
        } else {
            zs = x[(size_t)gs * NODED + (c - MEMD)];
            zp = x[(size_t)gp * NODED + (c - MEMD)];
            zn = x[(size_t)gn * NODED + (c - MEMD)];
        }
        g_zs[zoff + c] = __float2half_rn(zs * (1.0f + rts * wps[c] + bps[c]));
        g_zp[zoff + c] = __float2half_rn(zp * (1.0f + rtp * wpd[c] + bpd[c]));
        g_zn[zoff + c] = __float2half_rn(zn * (1.0f + rtn * wpd[c] + bpd[c]));
    }
}

// ---------------------------------------------------------------------------
// Kernel B: fused triple fp16 tensor-core GEMM + bias/ReLU/final-dot readout.
// Block tile 128x64, 8 warps (4M x 2N), warp tile 32x32 (m16n8k16 x 2x4),
// 3 accumulator sets, double-buffered cp.async K-pipeline (KB=32 halves).
// ---------------------------------------------------------------------------
__global__ __launch_bounds__(256) void gemm_readout(
    const float* __restrict__ bl, const float* __restrict__ bd,
    const float* __restrict__ wf,
    float* __restrict__ out)
{
    extern __shared__ __half sm[];
    uint32_t sbase = (uint32_t)__cvta_generic_to_shared(sm);

    int tid  = threadIdx.x;
    int wid  = tid >> 5, lane = tid & 31;
    int grp  = lane >> 2, qid = lane & 3;
    int wm   = wid & 3,  wn  = wid >> 2;
    int m0   = blockIdx.y * BM;
    int n0   = blockIdx.x * BN;

    const __half* zsrc[3] = { g_zs, g_zp, g_zn };
    const __half* wsrc[2] = { g_wl, g_wd };

    float acc[3][2][4][4];
    #pragma unroll
    for (int a = 0; a < 3; a++)
        #pragma unroll
        for (int b = 0; b < 2; b++)
            #pragma unroll
            for (int c = 0; c < 4; c++)
                #pragma unroll
                for (int d = 0; d < 4; d++) acc[a][b][c][d] = 0.f;

    auto load_chunk = [&](int ch, int buf) {
        int k0 = ch * KB;
        #pragma unroll
        for (int p = 0; p < 6; p++) {           // Z: 3 mats * 128 rows * 4 x 16B
            int id  = tid + p * 256;
            int mat = id >> 9;
            int rem = id & 511;
            int row = rem >> 2;
            int c8  = (rem & 3) << 3;           // half offset within row: 0,8,16,24
            const __half* src = zsrc[mat] + (size_t)(m0 + row) * DZ + k0 + c8;
            uint32_t dst = sbase + (uint32_t)((buf * ZBUF + (mat * 128 + row) * ZSTR + c8) * 2);
            asm volatile("cp.async.ca.shared.global [%0], [%1], 16;" :: "r"(dst), "l"(src));
        }
        #pragma unroll
        for (int p = 0; p < 2; p++) {           // W: 2 mats * 64 rows * 4 x 16B
            int id  = tid + p * 256;
            int mat = id >> 8;
            int rem = id & 255;
            int n   = rem >> 2;
            int c8  = (rem & 3) << 3;
            const __half* src = wsrc[mat] + (size_t)(n0 + n) * DZ + k0 + c8;
            uint32_t dst = sbase + (uint32_t)((ZTOT + buf * WBUF + (mat * 64 + n) * WSTR + c8) * 2);
            asm volatile("cp.async.ca.shared.global [%0], [%1], 16;" :: "r"(dst), "l"(src));
        }
        asm volatile("cp.async.commit_group;");
    };

    load_chunk(0, 0);
    int buf = 0;
    for (int ch = 0; ch < NCH; ch++) {
        if (ch + 1 < NCH) {
            load_chunk(ch + 1, buf ^ 1);
            asm volatile("cp.async.wait_group 1;");
        } else {
            asm volatile("cp.async.wait_group 0;");
        }
        __syncthreads();

        const __half* zb = sm + buf * ZBUF;
        const __half* wb = sm + ZTOT + buf * WBUF;

        #pragma unroll
        for (int kk = 0; kk < KB; kk += 16) {
            uint32_t afr[3][2][4];
            uint32_t bfr[2][4][2];
            #pragma unroll
            for (int mat = 0; mat < 3; mat++)
                #pragma unroll
                for (int mt = 0; mt < 2; mt++) {
                    int r = wm * 32 + mt * 16 + grp;
                    const __half* base = zb + mat * 128 * ZSTR;
                    afr[mat][mt][0] = *(const uint32_t*)(base + (r    ) * ZSTR + kk + 2 * qid);
                    afr[mat][mt][1] = *(const uint32_t*)(base + (r + 8) * ZSTR + kk + 2 * qid);
                    afr[mat][mt][2] = *(const uint32_t*)(base + (r    ) * ZSTR + kk + 8 + 2 * qid);
                    afr[mat][mt][3] = *(const uint32_t*)(base + (r + 8) * ZSTR + kk + 8 + 2 * qid);
                }
            #pragma unroll
            for (int mat = 0; mat < 2; mat++)
                #pragma unroll
                for (int nt = 0; nt < 4; nt++) {
                    int n = wn * 32 + nt * 8 + grp;
                    const __half* base = wb + mat * 64 * WSTR;
                    bfr[mat][nt][0] = *(const uint32_t*)(base + n * WSTR + kk + 2 * qid);
                    bfr[mat][nt][1] = *(const uint32_t*)(base + n * WSTR + kk + 8 + 2 * qid);
                }
            #pragma unroll
            for (int mt = 0; mt < 2; mt++)
                #pragma unroll
                for (int nt = 0; nt < 4; nt++) {
                    mma_f16(acc[0][mt][nt], afr[0][mt][0], afr[0][mt][1], afr[0][mt][2], afr[0][mt][3], bfr[0][nt][0], bfr[0][nt][1]);
                    mma_f16(acc[1][mt][nt], afr[1][mt][0], afr[1][mt][1], afr[1][mt][2], afr[1][mt][3], bfr[1][nt][0], bfr[1][nt][1]);
                    mma_f16(acc[2][mt][nt], afr[2][mt][0], afr[2][mt][1], afr[2][mt][2], afr[2][mt][3], bfr[1][nt][0], bfr[1][nt][1]);
                }
        }
        __syncthreads();
        buf ^= 1;
    }

    // --- epilogue: bias + relu + final-dot partials over this block's N range ---
    float pp[2][2] = {{0.f,0.f},{0.f,0.f}};
    float pn[2][2] = {{0.f,0.f},{0.f,0.f}};
    #pragma unroll
    for (int nt = 0; nt < 4; nt++) {
        #pragma unroll
        for (int j = 0; j < 2; j++) {
            int n = n0 + wn * 32 + nt * 8 + 2 * qid + j;
            float bias = bl[n] + bd[n];
            float wfn  = wf[n];
            #pragma unroll
            for (int mt = 0; mt < 2; mt++) {
                float c0 = acc[0][mt][nt][j]     + acc[1][mt][nt][j]     + bias;
                float c1 = acc[0][mt][nt][2 + j] + acc[1][mt][nt][2 + j] + bias;
                pp[mt][0] += fmaxf(c0, 0.f) * wfn;
                pp[mt][1] += fmaxf(c1, 0.f) * wfn;
                float d0 = acc[0][mt][nt][j]     + acc[2][mt][nt][j]     + bias;
                float d1 = acc[0][mt][nt][2 + j] + acc[2][mt][nt][2 + j] + bias;
                pn[mt][0] += fmaxf(d0, 0.f) * wfn;
                pn[mt][1] += fmaxf(d1, 0.f) * wfn;
            }
        }
    }
    // reduce across the quad
    #pragma unroll
    for (int s = 1; s < 4; s <<= 1) {
        #pragma unroll
        for (int mt = 0; mt < 2; mt++) {
            pp[mt][0] += __shfl_xor_sync(0xffffffffu, pp[mt][0], s);
            pp[mt][1] += __shfl_xor_sync(0xffffffffu, pp[mt][1], s);
            pn[mt][0] += __shfl_xor_sync(0xffffffffu, pn[mt][0], s);
            pn[mt][1] += __shfl_xor_sync(0xffffffffu, pn[mt][1], s);
        }
    }
    if (qid == 0) {
        #pragma unroll
        for (int mt = 0; mt < 2; mt++)
            #pragma unroll
            for (int rh = 0; rh < 2; rh++) {
                int e = m0 + wm * 32 + mt * 16 + rh * 8 + grp;
                if (e < NUM_E) {
                    atomicAdd(&out[e],         pp[mt][rh]);
                    atomicAdd(&out[NUM_E + e], pn[mt][rh]);
                }
            }
    }
}

// ---------------------------------------------------------------------------
extern "C" void kernel_launch(void* const* d_in, const int* in_sizes, int n_in,
                              void* d_out, int out_size) {
    const float* mem  = (const float*)d_in[0];
    const float* lu   = (const float*)d_in[1];
    const float* x    = (const float*)d_in[2];
    const float* bt   = (const float*)d_in[3];
    const float* wps  = (const float*)d_in[4];
    const float* bps  = (const float*)d_in[5];
    const float* wpd  = (const float*)d_in[6];
    const float* bpd  = (const float*)d_in[7];
    const float* wl   = (const float*)d_in[8];
    const float* bl   = (const float*)d_in[9];
    const float* wd   = (const float*)d_in[10];
    const float* bd   = (const float*)d_in[11];
    const float* wf   = (const float*)d_in[12];
    const float* bf   = (const float*)d_in[13];
    const int*   nid  = (const int*)d_in[14];
    const int*   idm  = (const int*)d_in[15];
    const int*   src  = (const int*)d_in[16];
    const int*   pds  = (const int*)d_in[17];
    const int*   nds  = (const int*)d_in[18];
    float* out = (float*)d_out;

    cudaFuncSetAttribute(gemm_readout,
                         cudaFuncAttributeMaxDynamicSharedMemorySize, SMEM_BYTES);

    convw<<<(DZ * DZ + 255) / 256, 256>>>(wl, wd);
    gather_scale<<<NUM_E, 128>>>(mem, lu, x, bt, wps, bps, wpd, bpd, bf,
                                 nid, idm, src, pds, nds, out);

    dim3 grid(DZ / BN, E_PAD / BM);   // (6, 782)
    gemm_readout<<<grid, 256, SMEM_BYTES>>>(bl, bd, wf, out);
}

// round 5
// speedup vs baseline: 4.3118x; 1.1246x over previous
#include <cuda_runtime.h>
#include <cuda_fp16.h>
#include <cstdint>

#define NUM_E 100000
#define DZ    384
#define MEMD  256
#define NODED 128
#define E_PAD 100096           // 782 * 128
#define BM 128
#define BN 64
#define KB 32                  // K halves per chunk
#define NCH (DZ/KB)            // 12 chunks

#define ZSTR 40                // padded row stride in halves (80 B) -> conflict-free
#define WSTR 40
#define ZBUF (3*128*ZSTR)      // 15360 halves per Z buffer
#define WBUF (2*64*WSTR)       // 5120 halves per W buffer
#define ZTOT (2*ZBUF)          // 30720
#define SMEM_BYTES ((ZTOT + 2*WBUF)*2)   // 81920 B

// fp16 scratch (zero-initialized .bss; rows >= NUM_E stay zero = safe padding)
__device__ __align__(16) __half g_zs[(size_t)E_PAD * DZ];
__device__ __align__(16) __half g_zp[(size_t)E_PAD * DZ];
__device__ __align__(16) __half g_zn[(size_t)E_PAD * DZ];
__device__ __align__(16) __half g_wl[DZ * DZ];
__device__ __align__(16) __half g_wd[DZ * DZ];
// per-edge resolved ids / rel-times: [which*NUM_E + e]
__device__ int   g_id3[3 * NUM_E];
__device__ float g_rt3[3 * NUM_E];

__device__ __forceinline__ void mma_f16(float* c,
    uint32_t a0, uint32_t a1, uint32_t a2, uint32_t a3,
    uint32_t b0, uint32_t b1)
{
    asm volatile(
        "mma.sync.aligned.m16n8k16.row.col.f32.f16.f16.f32 "
        "{%0,%1,%2,%3},{%4,%5,%6,%7},{%8,%9},{%0,%1,%2,%3};"
        : "+f"(c[0]), "+f"(c[1]), "+f"(c[2]), "+f"(c[3])
        : "r"(a0), "r"(a1), "r"(a2), "r"(a3), "r"(b0), "r"(b1));
}

__device__ __forceinline__ void ldsm4(uint32_t* r, uint32_t addr) {
    asm volatile("ldmatrix.sync.aligned.m8n8.x4.shared.b16 {%0,%1,%2,%3}, [%4];"
                 : "=r"(r[0]), "=r"(r[1]), "=r"(r[2]), "=r"(r[3]) : "r"(addr));
}

// ---------------------------------------------------------------------------
// Weight conversion to fp16.
// ---------------------------------------------------------------------------
__global__ void convw(const float* __restrict__ wl, const float* __restrict__ wd) {
    int i = blockIdx.x * blockDim.x + threadIdx.x;
    if (i < DZ * DZ) {
        g_wl[i] = __float2half_rn(wl[i]);
        g_wd[i] = __float2half_rn(wd[i]);
    }
}

// ---------------------------------------------------------------------------
// Resolve: per (edge, which) id chain + rel-time; fully parallel.
// ---------------------------------------------------------------------------
__global__ void resolve(
    const float* __restrict__ lu, const float* __restrict__ bt,
    const float* __restrict__ bfin,
    const int* __restrict__ nid, const int* __restrict__ idmap,
    const int* __restrict__ src, const int* __restrict__ pdst,
    const int* __restrict__ ndst,
    float* __restrict__ out)
{
    int e = blockIdx.x * blockDim.x + threadIdx.x;
    int w = blockIdx.y;
    if (e >= NUM_E) return;
    const int* idx = (w == 0) ? src : (w == 1) ? pdst : ndst;
    int g = nid[idmap[idx[e]]];
    g_id3[w * NUM_E + e] = g;
    g_rt3[w * NUM_E + e] = fabsf(lu[g] - bt[e]);
    if (w == 0) {
        float bfv = bfin[0];
        out[e]         = bfv;   // seed with b_final; GEMM atomically adds
        out[NUM_E + e] = bfv;
    }
}

// ---------------------------------------------------------------------------
// Gather: 96 threads per edge, float4 loads, half2 packed stores.
// Thread t handles columns 4t..4t+3.
// ---------------------------------------------------------------------------
__global__ __launch_bounds__(96) void gather96(
    const float* __restrict__ mem, const float* __restrict__ x,
    const float* __restrict__ wps, const float* __restrict__ bps,
    const float* __restrict__ wpd, const float* __restrict__ bpd,
    float* __restrict__ out)
{
    int e = blockIdx.x;
    int t = threadIdx.x;
    int c = t * 4;
    bool isMem = (c < MEMD);

    int gs = g_id3[e], gp = g_id3[NUM_E + e], gn = g_id3[2 * NUM_E + e];
    float rts = g_rt3[e], rtp = g_rt3[NUM_E + e], rtn = g_rt3[2 * NUM_E + e];

    float4 ws4 = *(const float4*)(wps + c);
    float4 bs4 = *(const float4*)(bps + c);
    float4 wd4 = *(const float4*)(wpd + c);
    float4 bd4 = *(const float4*)(bpd + c);

    float4 ss, sp, sn;
    ss.x = 1.f + rts * ws4.x + bs4.x; ss.y = 1.f + rts * ws4.y + bs4.y;
    ss.z = 1.f + rts * ws4.z + bs4.z; ss.w = 1.f + rts * ws4.w + bs4.w;
    sp.x = 1.f + rtp * wd4.x + bd4.x; sp.y = 1.f + rtp * wd4.y + bd4.y;
    sp.z = 1.f + rtp * wd4.z + bd4.z; sp.w = 1.f + rtp * wd4.w + bd4.w;
    sn.x = 1.f + rtn * wd4.x + bd4.x; sn.y = 1.f + rtn * wd4.y + bd4.y;
    sn.z = 1.f + rtn * wd4.z + bd4.z; sn.w = 1.f + rtn * wd4.w + bd4.w;

    float4 vs, vp, vn;
    if (isMem) {
        vs = *(const float4*)(mem + (size_t)gs * MEMD + c);
        vp = *(const float4*)(mem + (size_t)gp * MEMD + c);
        vn = *(const float4*)(mem + (size_t)gn * MEMD + c);
        float* msrc = out + 2 * NUM_E + (size_t)e * MEMD;
        float* mpos = out + 2 * NUM_E + (size_t)NUM_E * MEMD + (size_t)e * MEMD;
        *(float4*)(msrc + c) = vs;
        *(float4*)(mpos + c) = vp;
    } else {
        int cx = c - MEMD;
        vs = *(const float4*)(x + (size_t)gs * NODED + cx);
        vp = *(const float4*)(x + (size_t)gp * NODED + cx);
        vn = *(const float4*)(x + (size_t)gn * NODED + cx);
    }

    size_t off = (size_t)e * DZ + c;
    {
        __half2 h0 = __floats2half2_rn(vs.x * ss.x, vs.y * ss.y);
        __half2 h1 = __floats2half2_rn(vs.z * ss.z, vs.w * ss.w);
        uint2 u = make_uint2(*(uint32_t*)&h0, *(uint32_t*)&h1);
        *(uint2*)(g_zs + off) = u;
    }
    {
        __half2 h0 = __floats2half2_rn(vp.x * sp.x, vp.y * sp.y);
        __half2 h1 = __floats2half2_rn(vp.z * sp.z, vp.w * sp.w);
        uint2 u = make_uint2(*(uint32_t*)&h0, *(uint32_t*)&h1);
        *(uint2*)(g_zp + off) = u;
    }
    {
        __half2 h0 = __floats2half2_rn(vn.x * sn.x, vn.y * sn.y);
        __half2 h1 = __floats2half2_rn(vn.z * sn.z, vn.w * sn.w);
        uint2 u = make_uint2(*(uint32_t*)&h0, *(uint32_t*)&h1);
        *(uint2*)(g_zn + off) = u;
    }
}

// ---------------------------------------------------------------------------
// Kernel B: fused triple fp16 tensor-core GEMM + bias/ReLU/final-dot readout.
// Block tile 128x64, 8 warps (4M x 2N), warp tile 32x32 (m16n8k16 x 2x4),
// 3 accumulator sets, ldmatrix fragments, double-buffered cp.async pipeline.
// ---------------------------------------------------------------------------
__global__ __launch_bounds__(256) void gemm_readout(
    const float* __restrict__ bl, const float* __restrict__ bd,
    const float* __restrict__ wf,
    float* __restrict__ out)
{
    extern __shared__ __half sm[];
    uint32_t sbase = (uint32_t)__cvta_generic_to_shared(sm);

    int tid  = threadIdx.x;
    int wid  = tid >> 5, lane = tid & 31;
    int grp  = lane >> 2, qid = lane & 3;
    int wm   = wid & 3,  wn  = wid >> 2;
    int m0   = blockIdx.y * BM;
    int n0   = blockIdx.x * BN;

    // ldmatrix lane address components (in halves)
    int rowA = wm * 32 + (lane & 15);                      // + mt*16
    int kA   = (lane >> 4) * 8;
    int rowB = wn * 32 + (lane & 7) + ((lane >> 4) & 1) * 8;  // + pair*16
    int kB   = ((lane >> 3) & 1) * 8;

    const __half* zsrc[3] = { g_zs, g_zp, g_zn };
    const __half* wsrc[2] = { g_wl, g_wd };

    float acc[3][2][4][4];
    #pragma unroll
    for (int a = 0; a < 3; a++)
        #pragma unroll
        for (int b = 0; b < 2; b++)
            #pragma unroll
            for (int c = 0; c < 4; c++)
                #pragma unroll
                for (int d = 0; d < 4; d++) acc[a][b][c][d] = 0.f;

    auto load_chunk = [&](int ch, int buf) {
        int k0 = ch * KB;
        #pragma unroll
        for (int p = 0; p < 6; p++) {           // Z: 3 mats * 128 rows * 4 x 16B
            int id  = tid + p * 256;
            int mat = id >> 9;
            int rem = id & 511;
            int row = rem >> 2;
            int c8  = (rem & 3) << 3;
            const __half* src = zsrc[mat] + (size_t)(m0 + row) * DZ + k0 + c8;
            uint32_t dst = sbase + (uint32_t)((buf * ZBUF + (mat * 128 + row) * ZSTR + c8) * 2);
            asm volatile("cp.async.cg.shared.global [%0], [%1], 16;" :: "r"(dst), "l"(src));
        }
        #pragma unroll
        for (int p = 0; p < 2; p++) {           // W: 2 mats * 64 rows * 4 x 16B
            int id  = tid + p * 256;
            int mat = id >> 8;
            int rem = id & 255;
            int n   = rem >> 2;
            int c8  = (rem & 3) << 3;
            const __half* src = wsrc[mat] + (size_t)(n0 + n) * DZ + k0 + c8;
            uint32_t dst = sbase + (uint32_t)((ZTOT + buf * WBUF + (mat * 64 + n) * WSTR + c8) * 2);
            asm volatile("cp.async.cg.shared.global [%0], [%1], 16;" :: "r"(dst), "l"(src));
        }
        asm volatile("cp.async.commit_group;");
    };

    load_chunk(0, 0);
    int buf = 0;
    for (int ch = 0; ch < NCH; ch++) {
        if (ch + 1 < NCH) {
            load_chunk(ch + 1, buf ^ 1);
            asm volatile("cp.async.wait_group 1;");
        } else {
            asm volatile("cp.async.wait_group 0;");
        }
        __syncthreads();

        uint32_t zb = sbase + (uint32_t)(buf * ZBUF) * 2;
        uint32_t wb = sbase + (uint32_t)(ZTOT + buf * WBUF) * 2;

        #pragma unroll
        for (int kk = 0; kk < KB; kk += 16) {
            uint32_t afr[3][2][4];
            uint32_t bfr[2][2][4];
            #pragma unroll
            for (int mat = 0; mat < 3; mat++)
                #pragma unroll
                for (int mt = 0; mt < 2; mt++) {
                    uint32_t a = zb + (uint32_t)((mat * 128 * ZSTR +
                                 (rowA + mt * 16) * ZSTR + kk + kA) * 2);
                    ldsm4(afr[mat][mt], a);
                }
            #pragma unroll
            for (int mat = 0; mat < 2; mat++)
                #pragma unroll
                for (int pr = 0; pr < 2; pr++) {
                    uint32_t a = wb + (uint32_t)((mat * 64 * WSTR +
                                 (rowB + pr * 16) * WSTR + kk + kB) * 2);
                    ldsm4(bfr[mat][pr], a);
                }
            #pragma unroll
            for (int mt = 0; mt < 2; mt++)
                #pragma unroll
                for (int pr = 0; pr < 2; pr++)
                    #pragma unroll
                    for (int h = 0; h < 2; h++) {
                        int nt = pr * 2 + h;
                        mma_f16(acc[0][mt][nt], afr[0][mt][0], afr[0][mt][1], afr[0][mt][2], afr[0][mt][3],
                                bfr[0][pr][2 * h], bfr[0][pr][2 * h + 1]);
                        mma_f16(acc[1][mt][nt], afr[1][mt][0], afr[1][mt][1], afr[1][mt][2], afr[1][mt][3],
                                bfr[1][pr][2 * h], bfr[1][pr][2 * h + 1]);
                        mma_f16(acc[2][mt][nt], afr[2][mt][0], afr[2][mt][1], afr[2][mt][2], afr[2][mt][3],
                                bfr[1][pr][2 * h], bfr[1][pr][2 * h + 1]);
                    }
        }
        __syncthreads();
        buf ^= 1;
    }

    // --- epilogue: bias + relu + final-dot partials over this block's N range ---
    float pp[2][2] = {{0.f,0.f},{0.f,0.f}};
    float pn[2][2] = {{0.f,0.f},{0.f,0.f}};
    #pragma unroll
    for (int nt = 0; nt < 4; nt++) {
        #pragma unroll
        for (int j = 0; j < 2; j++) {
            int n = n0 + wn * 32 + nt * 8 + 2 * qid + j;
            float bias = bl[n] + bd[n];
            float wfn  = wf[n];
            #pragma unroll
            for (int mt = 0; mt < 2; mt++) {
                float c0 = acc[0][mt][nt][j]     + acc[1][mt][nt][j]     + bias;
                float c1 = acc[0][mt][nt][2 + j] + acc[1][mt][nt][2 + j] + bias;
                pp[mt][0] += fmaxf(c0, 0.f) * wfn;
                pp[mt][1] += fmaxf(c1, 0.f) * wfn;
                float d0 = acc[0][mt][nt][j]     + acc[2][mt][nt][j]     + bias;
                float d1 = acc[0][mt][nt][2 + j] + acc[2][mt][nt][2 + j] + bias;
                pn[mt][0] += fmaxf(d0, 0.f) * wfn;
                pn[mt][1] += fmaxf(d1, 0.f) * wfn;
            }
        }
    }
    // reduce across the quad
    #pragma unroll
    for (int s = 1; s < 4; s <<= 1) {
        #pragma unroll
        for (int mt = 0; mt < 2; mt++) {
            pp[mt][0] += __shfl_xor_sync(0xffffffffu, pp[mt][0], s);
            pp[mt][1] += __shfl_xor_sync(0xffffffffu, pp[mt][1], s);
            pn[mt][0] += __shfl_xor_sync(0xffffffffu, pn[mt][0], s);
            pn[mt][1] += __shfl_xor_sync(0xffffffffu, pn[mt][1], s);
        }
    }
    if (qid == 0) {
        #pragma unroll
        for (int mt = 0; mt < 2; mt++)
            #pragma unroll
            for (int rh = 0; rh < 2; rh++) {
                int e = m0 + wm * 32 + mt * 16 + rh * 8 + grp;
                if (e < NUM_E) {
                    atomicAdd(&out[e],         pp[mt][rh]);
                    atomicAdd(&out[NUM_E + e], pn[mt][rh]);
                }
            }
    }
}

// ---------------------------------------------------------------------------
extern "C" void kernel_launch(void* const* d_in, const int* in_sizes, int n_in,
                              void* d_out, int out_size) {
    const float* mem  = (const float*)d_in[0];
    const float* lu   = (const float*)d_in[1];
    const float* x    = (const float*)d_in[2];
    const float* bt   = (const float*)d_in[3];
    const float* wps  = (const float*)d_in[4];
    const float* bps  = (const float*)d_in[5];
    const float* wpd  = (const float*)d_in[6];
    const float* bpd  = (const float*)d_in[7];
    const float* wl   = (const float*)d_in[8];
    const float* bl   = (const float*)d_in[9];
    const float* wd   = (const float*)d_in[10];
    const float* bd   = (const float*)d_in[11];
    const float* wf   = (const float*)d_in[12];
    const float* bf   = (const float*)d_in[13];
    const int*   nid  = (const int*)d_in[14];
    const int*   idm  = (const int*)d_in[15];
    const int*   src  = (const int*)d_in[16];
    const int*   pds  = (const int*)d_in[17];
    const int*   nds  = (const int*)d_in[18];
    float* out = (float*)d_out;

    cudaFuncSetAttribute(gemm_readout,
                         cudaFuncAttributeMaxDynamicSharedMemorySize, SMEM_BYTES);

    convw<<<(DZ * DZ + 255) / 256, 256>>>(wl, wd);

    dim3 rgrid((NUM_E + 255) / 256, 3);
    resolve<<<rgrid, 256>>>(lu, bt, bf, nid, idm, src, pds, nds, out);

    gather96<<<NUM_E, 96>>>(mem, x, wps, bps, wpd, bpd, out);

    dim3 grid(DZ / BN, E_PAD / BM);   // (6, 782)
    gemm_readout<<<grid, 256, SMEM_BYTES>>>(bl, bd, wf, out);
}

// round 6
// speedup vs baseline: 4.6795x; 1.0853x over previous
#include <cuda_runtime.h>
#include <cuda_fp16.h>
#include <cstdint>

#define NUM_E 100000
#define DZ    384
#define MEMD  256
#define NODED 128
#define E_PAD 100096           // 782 * 128
#define BM 128
#define BN 64
#define KB 32                  // K halves per chunk
#define NCH (DZ/KB)            // 12 chunks
#define NSTAGE 3

#define ZSTR 40                // padded row stride in halves (80 B) -> conflict-free
#define WSTR 40
#define ZHALVES (3*128*ZSTR)   // 15360 halves per stage (Z part)
#define WHALVES (2*64*WSTR)    // 5120 halves per stage (W part)
#define STAGE_H (ZHALVES + WHALVES)       // 20480 halves
#define SMEM_BYTES (NSTAGE * STAGE_H * 2) // 122880 B

// fp16 scratch (zero-initialized .bss; rows >= NUM_E stay zero = safe padding)
__device__ __align__(16) __half g_zs[(size_t)E_PAD * DZ];
__device__ __align__(16) __half g_zp[(size_t)E_PAD * DZ];
__device__ __align__(16) __half g_zn[(size_t)E_PAD * DZ];
__device__ __align__(16) __half g_wl[DZ * DZ];
__device__ __align__(16) __half g_wd[DZ * DZ];
// per-edge resolved ids / rel-times: [which*NUM_E + e]
__device__ int   g_id3[3 * NUM_E];
__device__ float g_rt3[3 * NUM_E];

__device__ __forceinline__ void mma_f16(float* c,
    uint32_t a0, uint32_t a1, uint32_t a2, uint32_t a3,
    uint32_t b0, uint32_t b1)
{
    asm volatile(
        "mma.sync.aligned.m16n8k16.row.col.f32.f16.f16.f32 "
        "{%0,%1,%2,%3},{%4,%5,%6,%7},{%8,%9},{%0,%1,%2,%3};"
        : "+f"(c[0]), "+f"(c[1]), "+f"(c[2]), "+f"(c[3])
        : "r"(a0), "r"(a1), "r"(a2), "r"(a3), "r"(b0), "r"(b1));
}

__device__ __forceinline__ void ldsm4(uint32_t* r, uint32_t addr) {
    asm volatile("ldmatrix.sync.aligned.m8n8.x4.shared.b16 {%0,%1,%2,%3}, [%4];"
                 : "=r"(r[0]), "=r"(r[1]), "=r"(r[2]), "=r"(r[3]) : "r"(addr));
}

// ---------------------------------------------------------------------------
// Weight conversion to fp16.
// ---------------------------------------------------------------------------
__global__ void convw(const float* __restrict__ wl, const float* __restrict__ wd) {
    int i = blockIdx.x * blockDim.x + threadIdx.x;
    if (i < DZ * DZ) {
        g_wl[i] = __float2half_rn(wl[i]);
        g_wd[i] = __float2half_rn(wd[i]);
    }
}

// ---------------------------------------------------------------------------
// Resolve: per (edge, which) id chain + rel-time; fully parallel.
// ---------------------------------------------------------------------------
__global__ void resolve(
    const float* __restrict__ lu, const float* __restrict__ bt,
    const float* __restrict__ bfin,
    const int* __restrict__ nid, const int* __restrict__ idmap,
    const int* __restrict__ src, const int* __restrict__ pdst,
    const int* __restrict__ ndst,
    float* __restrict__ out)
{
    int e = blockIdx.x * blockDim.x + threadIdx.x;
    int w = blockIdx.y;
    if (e >= NUM_E) return;
    const int* idx = (w == 0) ? src : (w == 1) ? pdst : ndst;
    int g = nid[idmap[idx[e]]];
    g_id3[w * NUM_E + e] = g;
    g_rt3[w * NUM_E + e] = fabsf(lu[g] - bt[e]);
    if (w == 0) {
        float bfv = bfin[0];
        out[e]         = bfv;   // seed with b_final; GEMM atomically adds
        out[NUM_E + e] = bfv;
    }
}

// ---------------------------------------------------------------------------
// Gather: 96 threads per edge, float4 loads, half2 packed stores.
// ---------------------------------------------------------------------------
__global__ __launch_bounds__(96) void gather96(
    const float* __restrict__ mem, const float* __restrict__ x,
    const float* __restrict__ wps, const float* __restrict__ bps,
    const float* __restrict__ wpd, const float* __restrict__ bpd,
    float* __restrict__ out)
{
    int e = blockIdx.x;
    int t = threadIdx.x;
    int c = t * 4;
    bool isMem = (c < MEMD);

    int gs = g_id3[e], gp = g_id3[NUM_E + e], gn = g_id3[2 * NUM_E + e];
    float rts = g_rt3[e], rtp = g_rt3[NUM_E + e], rtn = g_rt3[2 * NUM_E + e];

    float4 ws4 = *(const float4*)(wps + c);
    float4 bs4 = *(const float4*)(bps + c);
    float4 wd4 = *(const float4*)(wpd + c);
    float4 bd4 = *(const float4*)(bpd + c);

    float4 ss, sp, sn;
    ss.x = 1.f + rts * ws4.x + bs4.x; ss.y = 1.f + rts * ws4.y + bs4.y;
    ss.z = 1.f + rts * ws4.z + bs4.z; ss.w = 1.f + rts * ws4.w + bs4.w;
    sp.x = 1.f + rtp * wd4.x + bd4.x; sp.y = 1.f + rtp * wd4.y + bd4.y;
    sp.z = 1.f + rtp * wd4.z + bd4.z; sp.w = 1.f + rtp * wd4.w + bd4.w;
    sn.x = 1.f + rtn * wd4.x + bd4.x; sn.y = 1.f + rtn * wd4.y + bd4.y;
    sn.z = 1.f + rtn * wd4.z + bd4.z; sn.w = 1.f + rtn * wd4.w + bd4.w;

    float4 vs, vp, vn;
    if (isMem) {
        vs = *(const float4*)(mem + (size_t)gs * MEMD + c);
        vp = *(const float4*)(mem + (size_t)gp * MEMD + c);
        vn = *(const float4*)(mem + (size_t)gn * MEMD + c);
        float* msrc = out + 2 * NUM_E + (size_t)e * MEMD;
        float* mpos = out + 2 * NUM_E + (size_t)NUM_E * MEMD + (size_t)e * MEMD;
        *(float4*)(msrc + c) = vs;
        *(float4*)(mpos + c) = vp;
    } else {
        int cx = c - MEMD;
        vs = *(const float4*)(x + (size_t)gs * NODED + cx);
        vp = *(const float4*)(x + (size_t)gp * NODED + cx);
        vn = *(const float4*)(x + (size_t)gn * NODED + cx);
    }

    size_t off = (size_t)e * DZ + c;
    {
        __half2 h0 = __floats2half2_rn(vs.x * ss.x, vs.y * ss.y);
        __half2 h1 = __floats2half2_rn(vs.z * ss.z, vs.w * ss.w);
        uint2 u = make_uint2(*(uint32_t*)&h0, *(uint32_t*)&h1);
        *(uint2*)(g_zs + off) = u;
    }
    {
        __half2 h0 = __floats2half2_rn(vp.x * sp.x, vp.y * sp.y);
        __half2 h1 = __floats2half2_rn(vp.z * sp.z, vp.w * sp.w);
        uint2 u = make_uint2(*(uint32_t*)&h0, *(uint32_t*)&h1);
        *(uint2*)(g_zp + off) = u;
    }
    {
        __half2 h0 = __floats2half2_rn(vn.x * sn.x, vn.y * sn.y);
        __half2 h1 = __floats2half2_rn(vn.z * sn.z, vn.w * sn.w);
        uint2 u = make_uint2(*(uint32_t*)&h0, *(uint32_t*)&h1);
        *(uint2*)(g_zn + off) = u;
    }
}

// ---------------------------------------------------------------------------
// Kernel B: fused triple fp16 tensor-core GEMM + readout.
// 512 threads = 16 warps (8M x 2N), warp tile 16x32, 3 accumulator sets,
// ldmatrix fragments, 3-stage cp.async pipeline.
// ---------------------------------------------------------------------------
__global__ __launch_bounds__(512, 1) void gemm_readout(
    const float* __restrict__ bl, const float* __restrict__ bd,
    const float* __restrict__ wf,
    float* __restrict__ out)
{
    extern __shared__ __half sm[];
    uint32_t sbase = (uint32_t)__cvta_generic_to_shared(sm);

    int tid  = threadIdx.x;
    int wid  = tid >> 5, lane = tid & 31;
    int grp  = lane >> 2, qid = lane & 3;
    int wm   = wid & 7,  wn  = wid >> 3;     // 8 M-warps x 2 N-warps
    int m0   = blockIdx.y * BM;
    int n0   = blockIdx.x * BN;

    // ldmatrix lane address components (in halves)
    int rowA = wm * 16 + (lane & 15);
    int kA   = (lane >> 4) * 8;
    int rowB = wn * 32 + (lane & 7) + ((lane >> 4) & 1) * 8;  // + pr*16
    int kB   = ((lane >> 3) & 1) * 8;

    const __half* zsrc[3] = { g_zs, g_zp, g_zn };
    const __half* wsrc[2] = { g_wl, g_wd };

    float acc[3][4][4];     // [set][nt][frag]
    #pragma unroll
    for (int a = 0; a < 3; a++)
        #pragma unroll
        for (int b = 0; b < 4; b++)
            #pragma unroll
            for (int c = 0; c < 4; c++) acc[a][b][c] = 0.f;

    auto load_chunk = [&](int ch, int stg) {
        int k0 = ch * KB;
        uint32_t sb = sbase + (uint32_t)(stg * STAGE_H) * 2;
        #pragma unroll
        for (int p = 0; p < 3; p++) {           // Z: 3 mats * 128 rows * 4 x 16B
            int id  = tid + p * 512;
            int mat = id >> 9;
            int rem = id & 511;
            int row = rem >> 2;
            int c8  = (rem & 3) << 3;
            const __half* src = zsrc[mat] + (size_t)(m0 + row) * DZ + k0 + c8;
            uint32_t dst = sb + (uint32_t)(((mat * 128 + row) * ZSTR + c8) * 2);
            asm volatile("cp.async.cg.shared.global [%0], [%1], 16;" :: "r"(dst), "l"(src));
        }
        {                                        // W: 2 mats * 64 rows * 4 x 16B
            int id  = tid;
            int mat = id >> 8;
            int rem = id & 255;
            int n   = rem >> 2;
            int c8  = (rem & 3) << 3;
            const __half* src = wsrc[mat] + (size_t)(n0 + n) * DZ + k0 + c8;
            uint32_t dst = sb + (uint32_t)((ZHALVES + (mat * 64 + n) * WSTR + c8) * 2);
            asm volatile("cp.async.cg.shared.global [%0], [%1], 16;" :: "r"(dst), "l"(src));
        }
        asm volatile("cp.async.commit_group;");
    };

    load_chunk(0, 0);
    load_chunk(1, 1);

    int stg = 0;
    for (int ch = 0; ch < NCH; ch++) {
        if (ch < NCH - 1) asm volatile("cp.async.wait_group 1;");
        else              asm volatile("cp.async.wait_group 0;");
        __syncthreads();

        // prefetch into the stage freed by compute(ch-1)
        if (ch + 2 < NCH) {
            int ns = stg + 2; if (ns >= NSTAGE) ns -= NSTAGE;
            load_chunk(ch + 2, ns);
        }

        uint32_t zb = sbase + (uint32_t)(stg * STAGE_H) * 2;
        uint32_t wb = zb + (uint32_t)ZHALVES * 2;

        #pragma unroll
        for (int kk = 0; kk < KB; kk += 16) {
            uint32_t afr[3][4];
            uint32_t bfr[2][2][4];
            #pragma unroll
            for (int mat = 0; mat < 3; mat++) {
                uint32_t a = zb + (uint32_t)(((mat * 128 + rowA) * ZSTR + kk + kA) * 2);
                ldsm4(afr[mat], a);
            }
            #pragma unroll
            for (int mat = 0; mat < 2; mat++)
                #pragma unroll
                for (int pr = 0; pr < 2; pr++) {
                    uint32_t a = wb + (uint32_t)(((mat * 64 + rowB + pr * 16) * WSTR + kk + kB) * 2);
                    ldsm4(bfr[mat][pr], a);
                }
            #pragma unroll
            for (int pr = 0; pr < 2; pr++)
                #pragma unroll
                for (int h = 0; h < 2; h++) {
                    int nt = pr * 2 + h;
                    mma_f16(acc[0][nt], afr[0][0], afr[0][1], afr[0][2], afr[0][3],
                            bfr[0][pr][2 * h], bfr[0][pr][2 * h + 1]);
                    mma_f16(acc[1][nt], afr[1][0], afr[1][1], afr[1][2], afr[1][3],
                            bfr[1][pr][2 * h], bfr[1][pr][2 * h + 1]);
                    mma_f16(acc[2][nt], afr[2][0], afr[2][1], afr[2][2], afr[2][3],
                            bfr[1][pr][2 * h], bfr[1][pr][2 * h + 1]);
                }
        }
        __syncthreads();
        stg = (stg + 1 == NSTAGE) ? 0 : stg + 1;
    }

    // --- epilogue: bias + relu + final-dot partials over this block's N range ---
    float pp0 = 0.f, pp1 = 0.f, pn0 = 0.f, pn1 = 0.f;
    #pragma unroll
    for (int nt = 0; nt < 4; nt++) {
        #pragma unroll
        for (int j = 0; j < 2; j++) {
            int n = n0 + wn * 32 + nt * 8 + 2 * qid + j;
            float bias = bl[n] + bd[n];
            float wfn  = wf[n];
            float c0 = acc[0][nt][j]     + acc[1][nt][j]     + bias;
            float c1 = acc[0][nt][2 + j] + acc[1][nt][2 + j] + bias;
            pp0 += fmaxf(c0, 0.f) * wfn;
            pp1 += fmaxf(c1, 0.f) * wfn;
            float d0 = acc[0][nt][j]     + acc[2][nt][j]     + bias;
            float d1 = acc[0][nt][2 + j] + acc[2][nt][2 + j] + bias;
            pn0 += fmaxf(d0, 0.f) * wfn;
            pn1 += fmaxf(d1, 0.f) * wfn;
        }
    }
    #pragma unroll
    for (int s = 1; s < 4; s <<= 1) {
        pp0 += __shfl_xor_sync(0xffffffffu, pp0, s);
        pp1 += __shfl_xor_sync(0xffffffffu, pp1, s);
        pn0 += __shfl_xor_sync(0xffffffffu, pn0, s);
        pn1 += __shfl_xor_sync(0xffffffffu, pn1, s);
    }
    if (qid == 0) {
        int e0 = m0 + wm * 16 + grp;
        int e1 = e0 + 8;
        if (e0 < NUM_E) {
            atomicAdd(&out[e0],         pp0);
            atomicAdd(&out[NUM_E + e0], pn0);
        }
        if (e1 < NUM_E) {
            atomicAdd(&out[e1],         pp1);
            atomicAdd(&out[NUM_E + e1], pn1);
        }
    }
}

// ---------------------------------------------------------------------------
extern "C" void kernel_launch(void* const* d_in, const int* in_sizes, int n_in,
                              void* d_out, int out_size) {
    const float* mem  = (const float*)d_in[0];
    const float* lu   = (const float*)d_in[1];
    const float* x    = (const float*)d_in[2];
    const float* bt   = (const float*)d_in[3];
    const float* wps  = (const float*)d_in[4];
    const float* bps  = (const float*)d_in[5];
    const float* wpd  = (const float*)d_in[6];
    const float* bpd  = (const float*)d_in[7];
    const float* wl   = (const float*)d_in[8];
    const float* bl   = (const float*)d_in[9];
    const float* wd   = (const float*)d_in[10];
    const float* bd   = (const float*)d_in[11];
    const float* wf   = (const float*)d_in[12];
    const float* bf   = (const float*)d_in[13];
    const int*   nid  = (const int*)d_in[14];
    const int*   idm  = (const int*)d_in[15];
    const int*   src  = (const int*)d_in[16];
    const int*   pds  = (const int*)d_in[17];
    const int*   nds  = (const int*)d_in[18];
    float* out = (float*)d_out;

    cudaFuncSetAttribute(gemm_readout,
                         cudaFuncAttributeMaxDynamicSharedMemorySize, SMEM_BYTES);

    convw<<<(DZ * DZ + 255) / 256, 256>>>(wl, wd);

    dim3 rgrid((NUM_E + 255) / 256, 3);
    resolve<<<rgrid, 256>>>(lu, bt, bf, nid, idm, src, pds, nds, out);

    gather96<<<NUM_E, 96>>>(mem, x, wps, bps, wpd, bpd, out);

    dim3 grid(DZ / BN, E_PAD / BM);   // (6, 782)
    gemm_readout<<<grid, 512, SMEM_BYTES>>>(bl, bd, wf, out);
}

// round 7
// speedup vs baseline: 5.2323x; 1.1181x over previous
#include <cuda_runtime.h>
#include <cuda_fp16.h>
#include <cstdint>

#define NUM_E 100000
#define DZ    384
#define MEMD  256
#define NODED 128
#define E_PAD 100096           // 1564 * 64
#define BM 64
#define BN 64
#define KB 64                  // K halves per chunk
#define NCH (DZ/KB)            // 6 chunks

#define ZSTR 72                // padded row stride in halves -> conflict-free
#define WSTR 72
#define ZHALVES (3*64*ZSTR)    // 13824 halves per stage (Z part)
#define WHALVES (2*64*WSTR)    // 9216 halves per stage (W part)
#define STAGE_H (ZHALVES + WHALVES)       // 23040 halves
#define SMEM_BYTES (2 * STAGE_H * 2)      // 92160 B

// fp16 scratch (zero-initialized .bss; rows >= NUM_E stay zero = safe padding)
__device__ __align__(16) __half g_zs[(size_t)E_PAD * DZ];
__device__ __align__(16) __half g_zp[(size_t)E_PAD * DZ];
__device__ __align__(16) __half g_zn[(size_t)E_PAD * DZ];
__device__ __align__(16) __half g_wl[DZ * DZ];
__device__ __align__(16) __half g_wd[DZ * DZ];
// per-edge resolved ids / rel-times: [which*NUM_E + e]
__device__ int   g_id3[3 * NUM_E];
__device__ float g_rt3[3 * NUM_E];

__device__ __forceinline__ void mma_f16(float* c,
    uint32_t a0, uint32_t a1, uint32_t a2, uint32_t a3,
    uint32_t b0, uint32_t b1)
{
    asm volatile(
        "mma.sync.aligned.m16n8k16.row.col.f32.f16.f16.f32 "
        "{%0,%1,%2,%3},{%4,%5,%6,%7},{%8,%9},{%0,%1,%2,%3};"
        : "+f"(c[0]), "+f"(c[1]), "+f"(c[2]), "+f"(c[3])
        : "r"(a0), "r"(a1), "r"(a2), "r"(a3), "r"(b0), "r"(b1));
}

__device__ __forceinline__ void ldsm4(uint32_t* r, uint32_t addr) {
    asm volatile("ldmatrix.sync.aligned.m8n8.x4.shared.b16 {%0,%1,%2,%3}, [%4];"
                 : "=r"(r[0]), "=r"(r[1]), "=r"(r[2]), "=r"(r[3]) : "r"(addr));
}

// ---------------------------------------------------------------------------
// Weight conversion to fp16.
// ---------------------------------------------------------------------------
__global__ void convw(const float* __restrict__ wl, const float* __restrict__ wd) {
    int i = blockIdx.x * blockDim.x + threadIdx.x;
    if (i < DZ * DZ) {
        g_wl[i] = __float2half_rn(wl[i]);
        g_wd[i] = __float2half_rn(wd[i]);
    }
}

// ---------------------------------------------------------------------------
// Resolve: per (edge, which) id chain + rel-time; fully parallel.
// ---------------------------------------------------------------------------
__global__ void resolve(
    const float* __restrict__ lu, const float* __restrict__ bt,
    const float* __restrict__ bfin,
    const int* __restrict__ nid, const int* __restrict__ idmap,
    const int* __restrict__ src, const int* __restrict__ pdst,
    const int* __restrict__ ndst,
    float* __restrict__ out)
{
    int e = blockIdx.x * blockDim.x + threadIdx.x;
    int w = blockIdx.y;
    if (e >= NUM_E) return;
    const int* idx = (w == 0) ? src : (w == 1) ? pdst : ndst;
    int g = nid[idmap[idx[e]]];
    g_id3[w * NUM_E + e] = g;
    g_rt3[w * NUM_E + e] = fabsf(lu[g] - bt[e]);
    if (w == 0) {
        float bfv = bfin[0];
        out[e]         = bfv;   // seed with b_final; GEMM atomically adds
        out[NUM_E + e] = bfv;
    }
}

// ---------------------------------------------------------------------------
// Gather: 96 threads per edge, float4 loads, half2 packed stores.
// ---------------------------------------------------------------------------
__global__ __launch_bounds__(96) void gather96(
    const float* __restrict__ mem, const float* __restrict__ x,
    const float* __restrict__ wps, const float* __restrict__ bps,
    const float* __restrict__ wpd, const float* __restrict__ bpd,
    float* __restrict__ out)
{
    int e = blockIdx.x;
    int t = threadIdx.x;
    int c = t * 4;
    bool isMem = (c < MEMD);

    int gs = g_id3[e], gp = g_id3[NUM_E + e], gn = g_id3[2 * NUM_E + e];
    float rts = g_rt3[e], rtp = g_rt3[NUM_E + e], rtn = g_rt3[2 * NUM_E + e];

    float4 ws4 = *(const float4*)(wps + c);
    float4 bs4 = *(const float4*)(bps + c);
    float4 wd4 = *(const float4*)(wpd + c);
    float4 bd4 = *(const float4*)(bpd + c);

    float4 ss, sp, sn;
    ss.x = 1.f + rts * ws4.x + bs4.x; ss.y = 1.f + rts * ws4.y + bs4.y;
    ss.z = 1.f + rts * ws4.z + bs4.z; ss.w = 1.f + rts * ws4.w + bs4.w;
    sp.x = 1.f + rtp * wd4.x + bd4.x; sp.y = 1.f + rtp * wd4.y + bd4.y;
    sp.z = 1.f + rtp * wd4.z + bd4.z; sp.w = 1.f + rtp * wd4.w + bd4.w;
    sn.x = 1.f + rtn * wd4.x + bd4.x; sn.y = 1.f + rtn * wd4.y + bd4.y;
    sn.z = 1.f + rtn * wd4.z + bd4.z; sn.w = 1.f + rtn * wd4.w + bd4.w;

    float4 vs, vp, vn;
    if (isMem) {
        vs = *(const float4*)(mem + (size_t)gs * MEMD + c);
        vp = *(const float4*)(mem + (size_t)gp * MEMD + c);
        vn = *(const float4*)(mem + (size_t)gn * MEMD + c);
        float* msrc = out + 2 * NUM_E + (size_t)e * MEMD;
        float* mpos = out + 2 * NUM_E + (size_t)NUM_E * MEMD + (size_t)e * MEMD;
        *(float4*)(msrc + c) = vs;
        *(float4*)(mpos + c) = vp;
    } else {
        int cx = c - MEMD;
        vs = *(const float4*)(x + (size_t)gs * NODED + cx);
        vp = *(const float4*)(x + (size_t)gp * NODED + cx);
        vn = *(const float4*)(x + (size_t)gn * NODED + cx);
    }

    size_t off = (size_t)e * DZ + c;
    {
        __half2 h0 = __floats2half2_rn(vs.x * ss.x, vs.y * ss.y);
        __half2 h1 = __floats2half2_rn(vs.z * ss.z, vs.w * ss.w);
        uint2 u = make_uint2(*(uint32_t*)&h0, *(uint32_t*)&h1);
        *(uint2*)(g_zs + off) = u;
    }
    {
        __half2 h0 = __floats2half2_rn(vp.x * sp.x, vp.y * sp.y);
        __half2 h1 = __floats2half2_rn(vp.z * sp.z, vp.w * sp.w);
        uint2 u = make_uint2(*(uint32_t*)&h0, *(uint32_t*)&h1);
        *(uint2*)(g_zp + off) = u;
    }
    {
        __half2 h0 = __floats2half2_rn(vn.x * sn.x, vn.y * sn.y);
        __half2 h1 = __floats2half2_rn(vn.z * sn.z, vn.w * sn.w);
        uint2 u = make_uint2(*(uint32_t*)&h0, *(uint32_t*)&h1);
        *(uint2*)(g_zn + off) = u;
    }
}

// ---------------------------------------------------------------------------
// Kernel B: fused triple fp16 tensor-core GEMM + readout.
// 256 threads = 8 warps (4M x 2N), warp tile 16x32, block tile 64x64,
// 3 accumulator sets, ldmatrix fragments, double-buffered KB=64 pipeline,
// 2 CTAs per SM for cross-CTA phase overlap.
// ---------------------------------------------------------------------------
__global__ __launch_bounds__(256, 2) void gemm_readout(
    const float* __restrict__ bl, const float* __restrict__ bd,
    const float* __restrict__ wf,
    float* __restrict__ out)
{
    extern __shared__ __half sm[];
    uint32_t sbase = (uint32_t)__cvta_generic_to_shared(sm);

    int tid  = threadIdx.x;
    int wid  = tid >> 5, lane = tid & 31;
    int grp  = lane >> 2, qid = lane & 3;
    int wm   = wid & 3,  wn  = wid >> 2;     // 4 M-warps x 2 N-warps
    int m0   = blockIdx.y * BM;
    int n0   = blockIdx.x * BN;

    // ldmatrix lane address components (in halves)
    int rowA = wm * 16 + (lane & 15);
    int kA   = (lane >> 4) * 8;
    int rowB = wn * 32 + (lane & 7) + ((lane >> 4) & 1) * 8;  // + pr*16
    int kB   = ((lane >> 3) & 1) * 8;

    const __half* zsrc[3] = { g_zs, g_zp, g_zn };
    const __half* wsrc[2] = { g_wl, g_wd };

    float acc[3][4][4];     // [set][nt][frag]
    #pragma unroll
    for (int a = 0; a < 3; a++)
        #pragma unroll
        for (int b = 0; b < 4; b++)
            #pragma unroll
            for (int c = 0; c < 4; c++) acc[a][b][c] = 0.f;

    auto load_chunk = [&](int ch, int stg) {
        int k0 = ch * KB;
        uint32_t sb = sbase + (uint32_t)(stg * STAGE_H) * 2;
        #pragma unroll
        for (int p = 0; p < 6; p++) {           // Z: 3 mats * 64 rows * 8 x 16B
            int id  = tid + p * 256;
            int mat = id >> 9;
            int rem = id & 511;
            int row = rem >> 3;
            int c8  = (rem & 7) << 3;
            const __half* src = zsrc[mat] + (size_t)(m0 + row) * DZ + k0 + c8;
            uint32_t dst = sb + (uint32_t)(((mat * 64 + row) * ZSTR + c8) * 2);
            asm volatile("cp.async.cg.shared.global [%0], [%1], 16;" :: "r"(dst), "l"(src));
        }
        #pragma unroll
        for (int p = 0; p < 4; p++) {           // W: 2 mats * 64 rows * 8 x 16B
            int id  = tid + p * 256;
            int mat = id >> 9;
            int rem = id & 511;
            int row = rem >> 3;
            int c8  = (rem & 7) << 3;
            const __half* src = wsrc[mat] + (size_t)(n0 + row) * DZ + k0 + c8;
            uint32_t dst = sb + (uint32_t)((ZHALVES + (mat * 64 + row) * WSTR + c8) * 2);
            asm volatile("cp.async.cg.shared.global [%0], [%1], 16;" :: "r"(dst), "l"(src));
        }
        asm volatile("cp.async.commit_group;");
    };

    load_chunk(0, 0);
    int stg = 0;
    for (int ch = 0; ch < NCH; ch++) {
        if (ch + 1 < NCH) {
            load_chunk(ch + 1, stg ^ 1);
            asm volatile("cp.async.wait_group 1;");
        } else {
            asm volatile("cp.async.wait_group 0;");
        }
        __syncthreads();

        uint32_t zb = sbase + (uint32_t)(stg * STAGE_H) * 2;
        uint32_t wb = zb + (uint32_t)ZHALVES * 2;

        #pragma unroll
        for (int kk = 0; kk < KB; kk += 16) {
            uint32_t afr[3][4];
            uint32_t bfr[2][2][4];
            #pragma unroll
            for (int mat = 0; mat < 3; mat++) {
                uint32_t a = zb + (uint32_t)(((mat * 64 + rowA) * ZSTR + kk + kA) * 2);
                ldsm4(afr[mat], a);
            }
            #pragma unroll
            for (int mat = 0; mat < 2; mat++)
                #pragma unroll
                for (int pr = 0; pr < 2; pr++) {
                    uint32_t a = wb + (uint32_t)(((mat * 64 + rowB + pr * 16) * WSTR + kk + kB) * 2);
                    ldsm4(bfr[mat][pr], a);
                }
            #pragma unroll
            for (int pr = 0; pr < 2; pr++)
                #pragma unroll
                for (int h = 0; h < 2; h++) {
                    int nt = pr * 2 + h;
                    mma_f16(acc[0][nt], afr[0][0], afr[0][1], afr[0][2], afr[0][3],
                            bfr[0][pr][2 * h], bfr[0][pr][2 * h + 1]);
                    mma_f16(acc[1][nt], afr[1][0], afr[1][1], afr[1][2], afr[1][3],
                            bfr[1][pr][2 * h], bfr[1][pr][2 * h + 1]);
                    mma_f16(acc[2][nt], afr[2][0], afr[2][1], afr[2][2], afr[2][3],
                            bfr[1][pr][2 * h], bfr[1][pr][2 * h + 1]);
                }
        }
        __syncthreads();
        stg ^= 1;
    }

    // --- epilogue: bias + relu + final-dot partials over this block's N range ---
    float pp0 = 0.f, pp1 = 0.f, pn0 = 0.f, pn1 = 0.f;
    #pragma unroll
    for (int nt = 0; nt < 4; nt++) {
        #pragma unroll
        for (int j = 0; j < 2; j++) {
            int n = n0 + wn * 32 + nt * 8 + 2 * qid + j;
            float bias = bl[n] + bd[n];
            float wfn  = wf[n];
            float c0 = acc[0][nt][j]     + acc[1][nt][j]     + bias;
            float c1 = acc[0][nt][2 + j] + acc[1][nt][2 + j] + bias;
            pp0 += fmaxf(c0, 0.f) * wfn;
            pp1 += fmaxf(c1, 0.f) * wfn;
            float d0 = acc[0][nt][j]     + acc[2][nt][j]     + bias;
            float d1 = acc[0][nt][2 + j] + acc[2][nt][2 + j] + bias;
            pn0 += fmaxf(d0, 0.f) * wfn;
            pn1 += fmaxf(d1, 0.f) * wfn;
        }
    }
    #pragma unroll
    for (int s = 1; s < 4; s <<= 1) {
        pp0 += __shfl_xor_sync(0xffffffffu, pp0, s);
        pp1 += __shfl_xor_sync(0xffffffffu, pp1, s);
        pn0 += __shfl_xor_sync(0xffffffffu, pn0, s);
        pn1 += __shfl_xor_sync(0xffffffffu, pn1, s);
    }
    if (qid == 0) {
        int e0 = m0 + wm * 16 + grp;
        int e1 = e0 + 8;
        if (e0 < NUM_E) {
            atomicAdd(&out[e0],         pp0);
            atomicAdd(&out[NUM_E + e0], pn0);
        }
        if (e1 < NUM_E) {
            atomicAdd(&out[e1],         pp1);
            atomicAdd(&out[NUM_E + e1], pn1);
        }
    }
}

// ---------------------------------------------------------------------------
extern "C" void kernel_launch(void* const* d_in, const int* in_sizes, int n_in,
                              void* d_out, int out_size) {
    const float* mem  = (const float*)d_in[0];
    const float* lu   = (const float*)d_in[1];
    const float* x    = (const float*)d_in[2];
    const float* bt   = (const float*)d_in[3];
    const float* wps  = (const float*)d_in[4];
    const float* bps  = (const float*)d_in[5];
    const float* wpd  = (const float*)d_in[6];
    const float* bpd  = (const float*)d_in[7];
    const float* wl   = (const float*)d_in[8];
    const float* bl   = (const float*)d_in[9];
    const float* wd   = (const float*)d_in[10];
    const float* bd   = (const float*)d_in[11];
    const float* wf   = (const float*)d_in[12];
    const float* bf   = (const float*)d_in[13];
    const int*   nid  = (const int*)d_in[14];
    const int*   idm  = (const int*)d_in[15];
    const int*   src  = (const int*)d_in[16];
    const int*   pds  = (const int*)d_in[17];
    const int*   nds  = (const int*)d_in[18];
    float* out = (float*)d_out;

    cudaFuncSetAttribute(gemm_readout,
                         cudaFuncAttributeMaxDynamicSharedMemorySize, SMEM_BYTES);

    convw<<<(DZ * DZ + 255) / 256, 256>>>(wl, wd);

    dim3 rgrid((NUM_E + 255) / 256, 3);
    resolve<<<rgrid, 256>>>(lu, bt, bf, nid, idm, src, pds, nds, out);

    gather96<<<NUM_E, 96>>>(mem, x, wps, bps, wpd, bpd, out);

    dim3 grid(DZ / BN, E_PAD / BM);   // (6, 1564)
    gemm_readout<<<grid, 256, SMEM_BYTES>>>(bl, bd, wf, out);
}